// round 3
// baseline (speedup 1.0000x reference)
#include <cuda_runtime.h>

#define NPTS 2048
#define SMEM_FLOATS 45184
#define SMEM_BYTES (SMEM_FLOATS * 4)

// -------- scratch (device globals: allocation-free) --------
__device__ float d_WkT[64 * 128];
__device__ float d_WvT[64 * 128];
__device__ float d_WqT[64 * 128];
__device__ float d_Wr[128];
__device__ float d_Wf1T[384 * 128];
__device__ float d_Wf2T[128 * 128];
__device__ float d_bf2s[128];
__device__ float d_q[NPTS * 384];

// ---------------- prep: fold weights ----------------
// Wk_eff = Wk @ We2 @ We1 (128x64), stored transposed [c][o]; same for v,q.
// Wr = Wr2 @ Wr1 (128). Wf1T = Wf1^T. Wf2T = (Wf2/SCALE)^T. bf2s = bf2/SCALE.
__global__ void prep_kernel(const float* __restrict__ We1, const float* __restrict__ We2,
                            const float* __restrict__ Wq,  const float* __restrict__ Wk,
                            const float* __restrict__ Wv,  const float* __restrict__ Wr1,
                            const float* __restrict__ Wr2, const float* __restrict__ Wf1,
                            const float* __restrict__ Wf2, const float* __restrict__ bf2) {
    __shared__ float sWcol[128];            // We21[:, c] for this block's c
    const float invS = 0.08838834764831845f;  // 1/sqrt(128)
    int c = blockIdx.x;                     // 0..63
    int t = threadIdx.x;                    // 0..127
    float a = 0.f;
    for (int e = 0; e < 128; e++) a += We2[t * 128 + e] * We1[e * 64 + c];
    sWcol[t] = a;                           // We21[t][c]
    __syncthreads();
    float ak = 0.f, av = 0.f, aq = 0.f;
    for (int x = 0; x < 128; x++) {
        float w = sWcol[x];
        ak += Wk[t * 128 + x] * w;
        av += Wv[t * 128 + x] * w;
        aq += Wq[t * 128 + x] * w;
    }
    d_WkT[c * 128 + t] = ak;
    d_WvT[c * 128 + t] = av;
    d_WqT[c * 128 + t] = aq;
#pragma unroll
    for (int u = 0; u < 6; u++) { int cc = c * 6 + u; d_Wf1T[cc * 128 + t] = Wf1[t * 384 + cc]; }
#pragma unroll
    for (int u = 0; u < 2; u++) { int cc = c * 2 + u; d_Wf2T[cc * 128 + t] = Wf2[t * 128 + cc] * invS; }
    if (c == 0) {
        float r = 0.f;
        for (int m = 0; m < 64; m++) r += Wr2[t * 64 + m] * Wr1[m];
        d_Wr[t] = r;
        d_bf2s[t] = bf2[t] * invS;
    }
}

// ---------------- per-point q (from s=0 column of group_fts) ----------------
__global__ void q_kernel(const float* __restrict__ gfts) {
    int p = blockIdx.x;             // b*1024 + n
    int b = p >> 10, n = p & 1023;
    int o = threadIdx.x;            // 128 threads
    const float* gbase = gfts + (size_t)b * 6291456u + (size_t)n * 32u;
    float acc0 = 0.f, acc1 = 0.f, acc2 = 0.f;
    for (int c = 0; c < 64; c++) {
        float w = d_WqT[c * 128 + o];
        acc0 += w * gbase[c * 98304 + 0 * 32768];
        acc1 += w * gbase[c * 98304 + 1 * 32768];
        acc2 += w * gbase[c * 98304 + 2 * 32768];
    }
    d_q[p * 384 + o * 3 + 0] = acc0;
    d_q[p * 384 + o * 3 + 1] = acc1;
    d_q[p * 384 + o * 3 + 2] = acc2;
}

// ---------------- warp reductions ----------------
__device__ __forceinline__ float wmax(float v) {
#pragma unroll
    for (int m = 16; m; m >>= 1) v = fmaxf(v, __shfl_xor_sync(0xffffffffu, v, m));
    return v;
}
__device__ __forceinline__ float wsum(float v) {
#pragma unroll
    for (int m = 16; m; m >>= 1) v += __shfl_xor_sync(0xffffffffu, v, m);
    return v;
}

// ---------------- fused main kernel: one CTA per point ----------------
__global__ __launch_bounds__(256, 1)
void main_kernel(const float* __restrict__ gxyz, const float* __restrict__ gfts,
                 const float* __restrict__ qxyz, const float* __restrict__ Wstd,
                 const float* __restrict__ bf1, float* __restrict__ out) {
    extern __shared__ float smf[];
    float* sG    = smf;             // [64][3][32]  phase1         (6144)
    float* sWk   = smf + 6144;      // [64][128]    phase1         (8192)
    float* sWv   = smf + 14336;     // [64][128]    phase1         (8192)
    float* sA2   = smf;             // [384][32]    phase2+  alias (12288)
    float* sVpr  = smf + 12288;     // [128][3][32] phase2+  alias (12288)
    float* sXr   = smf + 24576;     // [3][32]
    float* sQ    = smf + 24672;     // [384]
    float* sWr   = smf + 25056;     // [128]
    float* sWstd = smf + 25184;     // [3][128]
    float* sZp   = smf + 25568;     // [8][32][9]
    float* sZ    = smf + 27872;     // [9][32]
    float* sH    = smf + 28160;     // [128][36] padded
    float* sWt   = smf + 32768;     // [64][128] tile buffer
    float* sAx   = smf + 40960;     // [128][33] padded

    const int p = blockIdx.x;
    const int b = p >> 10, n = p & 1023;
    const int tid = threadIdx.x;

    // ---- cooperative loads ----
    {
        const float4* gb4 = (const float4*)(gfts + (size_t)b * 6291456u + (size_t)n * 32u);
        for (int idx = tid; idx < 1536; idx += 256) {
            int c = idx / 24;
            int rem = idx - c * 24;
            int d = rem >> 3, s4 = rem & 7;
            ((float4*)sG)[idx] = gb4[c * 24576 + d * 8192 + s4];
        }
        for (int idx = tid; idx < 2048; idx += 256) {
            ((float4*)sWk)[idx] = ((const float4*)d_WkT)[idx];
            ((float4*)sWv)[idx] = ((const float4*)d_WvT)[idx];
        }
        for (int idx = tid; idx < 384; idx += 256) {
            sQ[idx] = d_q[p * 384 + idx];
            sWstd[idx] = Wstd[idx];
        }
        if (tid < 128) sWr[tid] = d_Wr[tid];
        if (tid < 96) {
            int d = tid >> 5, s = tid & 31;
            sXr[tid] = gxyz[((size_t)p * 32 + s) * 3 + d] - qxyz[(size_t)p * 3 + d];
        }
    }
    __syncthreads();

    const int s = tid & 31, r = tid >> 5, o0 = r << 4;

    // ---- phase 2: k, v (two 128x64 GEMVs per s) ----
    float at[16][3], vp[16][3];
#pragma unroll
    for (int i = 0; i < 16; i++) {
        at[i][0] = at[i][1] = at[i][2] = 0.f;
        vp[i][0] = vp[i][1] = vp[i][2] = 0.f;
    }
    for (int c = 0; c < 64; c++) {
        float g0 = sG[c * 96 + s];
        float g1 = sG[c * 96 + 32 + s];
        float g2 = sG[c * 96 + 64 + s];
        const float4* wk4 = (const float4*)(sWk + c * 128 + o0);
        const float4* wv4 = (const float4*)(sWv + c * 128 + o0);
#pragma unroll
        for (int j = 0; j < 4; j++) {
            float4 wk = wk4[j];
            float4 wv = wv4[j];
            int i0 = j * 4;
            at[i0 + 0][0] += wk.x * g0; at[i0 + 0][1] += wk.x * g1; at[i0 + 0][2] += wk.x * g2;
            at[i0 + 1][0] += wk.y * g0; at[i0 + 1][1] += wk.y * g1; at[i0 + 1][2] += wk.y * g2;
            at[i0 + 2][0] += wk.z * g0; at[i0 + 2][1] += wk.z * g1; at[i0 + 2][2] += wk.z * g2;
            at[i0 + 3][0] += wk.w * g0; at[i0 + 3][1] += wk.w * g1; at[i0 + 3][2] += wk.w * g2;
            vp[i0 + 0][0] += wv.x * g0; vp[i0 + 0][1] += wv.x * g1; vp[i0 + 0][2] += wv.x * g2;
            vp[i0 + 1][0] += wv.y * g0; vp[i0 + 1][1] += wv.y * g1; vp[i0 + 1][2] += wv.y * g2;
            vp[i0 + 2][0] += wv.z * g0; vp[i0 + 2][1] += wv.z * g1; vp[i0 + 2][2] += wv.z * g2;
            vp[i0 + 3][0] += wv.w * g0; vp[i0 + 3][1] += wv.w * g1; vp[i0 + 3][2] += wv.w * g2;
        }
    }

    // ---- phase 3: attn = q - k + pr ; vpr = v + pr ----
#pragma unroll
    for (int i = 0; i < 16; i++) {
        float wr = sWr[o0 + i];
#pragma unroll
        for (int d = 0; d < 3; d++) {
            float pr = wr * sXr[d * 32 + s];
            float a = sQ[(o0 + i) * 3 + d] - at[i][d] + pr;
            float v = vp[i][d] + pr;
            at[i][d] = a;
            vp[i][d] = v;
        }
    }
    __syncthreads();   // all reads of sG/sWk/sWv complete before aliased writes

#pragma unroll
    for (int i = 0; i < 16; i++) {
        sVpr[(o0 + i) * 96 + s]      = vp[i][0];
        sVpr[(o0 + i) * 96 + 32 + s] = vp[i][1];
        sVpr[(o0 + i) * 96 + 64 + s] = vp[i][2];
    }

    // ---- phase 4: z0 partials ----
    {
        float pz[9];
#pragma unroll
        for (int jk = 0; jk < 9; jk++) pz[jk] = 0.f;
#pragma unroll
        for (int i = 0; i < 16; i++) {
            float w0 = sWstd[o0 + i];
            float w1 = sWstd[128 + o0 + i];
            float w2 = sWstd[256 + o0 + i];
#pragma unroll
            for (int k = 0; k < 3; k++) {
                float a = at[i][k];
                pz[0 * 3 + k] += w0 * a;
                pz[1 * 3 + k] += w1 * a;
                pz[2 * 3 + k] += w2 * a;
            }
        }
#pragma unroll
        for (int jk = 0; jk < 9; jk++) sZp[(r * 32 + s) * 9 + jk] = pz[jk];
    }
    __syncthreads();
    if (r == 0) {
#pragma unroll
        for (int jk = 0; jk < 9; jk++) {
            float v = 0.f;
#pragma unroll
            for (int rr = 0; rr < 8; rr++) v += sZp[(rr * 32 + s) * 9 + jk];
            sZ[jk * 32 + s] = v;
        }
    }
    __syncthreads();

    // ---- phase 6: attn2 = attn @ z0, store flattened [384][32] ----
    {
        float z[9];
#pragma unroll
        for (int jk = 0; jk < 9; jk++) z[jk] = sZ[jk * 32 + s];
#pragma unroll
        for (int i = 0; i < 16; i++) {
#pragma unroll
            for (int k = 0; k < 3; k++) {
                float a2 = at[i][0] * z[0 * 3 + k] + at[i][1] * z[1 * 3 + k] + at[i][2] * z[2 * 3 + k];
                sA2[((o0 + i) * 3 + k) * 32 + s] = a2;
            }
        }
    }
    __syncthreads();

    // ---- phase 7: f1 (128x384 GEMM over s=32), tiled weights ----
    const int oo = tid & 127, sg = tid >> 7;
    float hh[16];
#pragma unroll
    for (int q = 0; q < 16; q++) hh[q] = 0.f;
    for (int ct = 0; ct < 6; ct++) {
        __syncthreads();
        const float4* src = (const float4*)(d_Wf1T + ct * 8192);
        float4* dst = (float4*)sWt;
#pragma unroll
        for (int kk = 0; kk < 8; kk++) dst[tid + kk * 256] = src[tid + kk * 256];
        __syncthreads();
        for (int cc = 0; cc < 64; cc++) {
            float w = sWt[cc * 128 + oo];
            const float4* av4 = (const float4*)(sA2 + (ct * 64 + cc) * 32 + sg * 16);
#pragma unroll
            for (int qq = 0; qq < 4; qq++) {
                float4 a = av4[qq];
                hh[qq * 4 + 0] += w * a.x;
                hh[qq * 4 + 1] += w * a.y;
                hh[qq * 4 + 2] += w * a.z;
                hh[qq * 4 + 3] += w * a.w;
            }
        }
    }
    {
        float bb = bf1[oo];
#pragma unroll
        for (int q = 0; q < 16; q++) hh[q] = fmaxf(hh[q] + bb, 0.f);
#pragma unroll
        for (int q = 0; q < 16; q++) sH[oo * 36 + sg * 16 + q] = hh[q];
    }

    // ---- phase 8: f2 (128x128) ----
    float aa[16];
#pragma unroll
    for (int q = 0; q < 16; q++) aa[q] = 0.f;
    for (int ct = 0; ct < 2; ct++) {
        __syncthreads();
        const float4* src = (const float4*)(d_Wf2T + ct * 8192);
        float4* dst = (float4*)sWt;
#pragma unroll
        for (int kk = 0; kk < 8; kk++) dst[tid + kk * 256] = src[tid + kk * 256];
        __syncthreads();
        for (int cc = 0; cc < 64; cc++) {
            float w = sWt[cc * 128 + oo];
            const float4* hv4 = (const float4*)(sH + (ct * 64 + cc) * 36 + sg * 16);
#pragma unroll
            for (int qq = 0; qq < 4; qq++) {
                float4 h = hv4[qq];
                aa[qq * 4 + 0] += w * h.x;
                aa[qq * 4 + 1] += w * h.y;
                aa[qq * 4 + 2] += w * h.z;
                aa[qq * 4 + 3] += w * h.w;
            }
        }
    }
    {
        float bb = d_bf2s[oo];   // scale 1/sqrt(128) already folded into Wf2T and bf2s
#pragma unroll
        for (int q = 0; q < 16; q++) sAx[oo * 33 + sg * 16 + q] = aa[q] + bb;
    }
    __syncthreads();

    // ---- phase 9: softmax over s + weighted sum over s ----
    for (int i = 0; i < 16; i++) {
        int o = o0 + i;
        float x = sAx[o * 33 + s];
        float m = wmax(x);
        float e = __expf(x - m);
        float denom = wsum(e);
        float w = e / denom;
#pragma unroll
        for (int d = 0; d < 3; d++) {
            float val = w * sVpr[o * 96 + d * 32 + s];
            float rs = wsum(val);
            if (s == 0) out[(((size_t)b * 128 + o) * 3 + d) * 1024 + n] = rs;
        }
    }
}

extern "C" void kernel_launch(void* const* d_in, const int* in_sizes, int n_in,
                              void* d_out, int out_size) {
    (void)in_sizes; (void)n_in; (void)out_size;
    const float* gxyz = (const float*)d_in[0];
    const float* gfts = (const float*)d_in[1];
    const float* qxyz = (const float*)d_in[2];
    cudaFuncSetAttribute(main_kernel, cudaFuncAttributeMaxDynamicSharedMemorySize, SMEM_BYTES);
    prep_kernel<<<64, 128>>>((const float*)d_in[3],  (const float*)d_in[4],
                             (const float*)d_in[5],  (const float*)d_in[6],
                             (const float*)d_in[7],  (const float*)d_in[8],
                             (const float*)d_in[9],  (const float*)d_in[11],
                             (const float*)d_in[13], (const float*)d_in[14]);
    q_kernel<<<NPTS, 128>>>(gfts);
    main_kernel<<<NPTS, 256, SMEM_BYTES>>>(gxyz, gfts, qxyz,
                                           (const float*)d_in[10],
                                           (const float*)d_in[12],
                                           (float*)d_out);
}

// round 5
// speedup vs baseline: 1.1162x; 1.1162x over previous
#include <cuda_runtime.h>

#define NPTS 2048
#define SMEM_FLOATS 45184
#define SMEM_BYTES (SMEM_FLOATS * 4)

// -------- scratch (device globals: allocation-free) --------
__device__ float d_We21[128 * 64];
__device__ float d_WkT[64 * 128];
__device__ float d_WvT[64 * 128];
__device__ float d_WqT[64 * 128];
__device__ float d_Wr[128];
__device__ float d_Wf1T[384 * 128];
__device__ float d_Wf2T[128 * 128];
__device__ float d_bf2s[128];
__device__ float d_q[NPTS * 384];

// -------- packed f32x2 helpers (SASS FFMA2 path, PTX-only) --------
__device__ __forceinline__ void ffma2(unsigned long long& d,
                                      unsigned long long a,
                                      unsigned long long b) {
    asm("fma.rn.f32x2 %0, %1, %2, %0;" : "+l"(d) : "l"(a), "l"(b));
}
__device__ __forceinline__ unsigned long long pack2(float x) {
    unsigned long long r;
    asm("mov.b64 %0, {%1, %1};" : "=l"(r) : "f"(x));
    return r;
}
__device__ __forceinline__ float2 unpack2(unsigned long long v) {
    float2 f;
    asm("mov.b64 {%0, %1}, %2;" : "=f"(f.x), "=f"(f.y) : "l"(v));
    return f;
}

// ---------------- prep1: We21 = We2 @ We1  (128x64) ----------------
// block = row t (128 blocks), thread = col c (64). We2 row broadcast, We1 coalesced.
__global__ void prep1_kernel(const float* __restrict__ We1, const float* __restrict__ We2) {
    int t = blockIdx.x, c = threadIdx.x;
    float a = 0.f;
#pragma unroll 8
    for (int e = 0; e < 128; e++) a += We2[t * 128 + e] * We1[e * 64 + c];
    d_We21[t * 64 + c] = a;
}

// ---------------- prep2: fold q/k/v + transpose f1/f2 + Wr ----------------
// block = output row o (128 blocks), thread = c (64). W rows broadcast, We21 coalesced.
__global__ void prep2_kernel(const float* __restrict__ Wq, const float* __restrict__ Wk,
                             const float* __restrict__ Wv, const float* __restrict__ Wr1,
                             const float* __restrict__ Wr2, const float* __restrict__ Wf1,
                             const float* __restrict__ Wf2, const float* __restrict__ bf2) {
    const float invS = 0.08838834764831845f;  // 1/sqrt(128)
    int o = blockIdx.x, c = threadIdx.x;
    float ak = 0.f, av = 0.f, aq = 0.f;
#pragma unroll 8
    for (int x = 0; x < 128; x++) {
        float w21 = d_We21[x * 64 + c];
        ak += Wk[o * 128 + x] * w21;
        av += Wv[o * 128 + x] * w21;
        aq += Wq[o * 128 + x] * w21;
    }
    d_WkT[c * 128 + o] = ak;
    d_WvT[c * 128 + o] = av;
    d_WqT[c * 128 + o] = aq;
#pragma unroll
    for (int u = 0; u < 6; u++) { int cc = u * 64 + c; d_Wf1T[cc * 128 + o] = Wf1[o * 384 + cc]; }
#pragma unroll
    for (int u = 0; u < 2; u++) { int cc = u * 64 + c; d_Wf2T[cc * 128 + o] = Wf2[o * 128 + cc] * invS; }
    __shared__ float red[64];
    red[c] = Wr2[o * 64 + c] * Wr1[c];
    __syncthreads();
    if (c == 0) {
        float r = 0.f;
#pragma unroll
        for (int i = 0; i < 64; i++) r += red[i];
        d_Wr[o] = r;
        d_bf2s[o] = bf2[o] * invS;
    }
}

// ---------------- per-point q (from s=0 column of group_fts) ----------------
__global__ void q_kernel(const float* __restrict__ gfts) {
    int p = blockIdx.x;             // b*1024 + n
    int b = p >> 10, n = p & 1023;
    int o = threadIdx.x;            // 128 threads
    const float* gbase = gfts + (size_t)b * 6291456u + (size_t)n * 32u;
    float acc0 = 0.f, acc1 = 0.f, acc2 = 0.f;
#pragma unroll 4
    for (int c = 0; c < 64; c++) {
        float w = d_WqT[c * 128 + o];
        acc0 += w * gbase[c * 98304 + 0 * 32768];
        acc1 += w * gbase[c * 98304 + 1 * 32768];
        acc2 += w * gbase[c * 98304 + 2 * 32768];
    }
    d_q[p * 384 + o * 3 + 0] = acc0;
    d_q[p * 384 + o * 3 + 1] = acc1;
    d_q[p * 384 + o * 3 + 2] = acc2;
}

// ---------------- warp reductions ----------------
__device__ __forceinline__ float wmax(float v) {
#pragma unroll
    for (int m = 16; m; m >>= 1) v = fmaxf(v, __shfl_xor_sync(0xffffffffu, v, m));
    return v;
}
__device__ __forceinline__ float wsum(float v) {
#pragma unroll
    for (int m = 16; m; m >>= 1) v += __shfl_xor_sync(0xffffffffu, v, m);
    return v;
}

// ---------------- fused main kernel: one CTA per point ----------------
__global__ __launch_bounds__(256, 1)
void main_kernel(const float* __restrict__ gxyz, const float* __restrict__ gfts,
                 const float* __restrict__ qxyz, const float* __restrict__ Wstd,
                 const float* __restrict__ bf1, float* __restrict__ out) {
    extern __shared__ float smf[];
    float* sG    = smf;             // [64][3][32]  phase1         (6144)
    float* sWk   = smf + 6144;      // [64][128]    phase1         (8192)
    float* sWv   = smf + 14336;     // [64][128]    phase1         (8192)
    float* sA2   = smf;             // [384][32]    phase2+  alias (12288)
    float* sVpr  = smf + 12288;     // [128][3][32] phase2+  alias (12288)
    float* sXr   = smf + 24576;     // [3][32]
    float* sQ    = smf + 24672;     // [384]
    float* sWr   = smf + 25056;     // [128]
    float* sWstd = smf + 25184;     // [3][128]
    float* sZp   = smf + 25568;     // [8][32][9]
    float* sZ    = smf + 27872;     // [9][32]
    float* sH    = smf + 28160;     // [128][36] padded
    float* sWt   = smf + 32768;     // [64][128] tile buffer
    float* sAx   = smf + 40960;     // [128][33] padded

    const int p = blockIdx.x;
    const int b = p >> 10, n = p & 1023;
    const int tid = threadIdx.x;

    // ---- cooperative loads ----
    {
        const float4* gb4 = (const float4*)(gfts + (size_t)b * 6291456u + (size_t)n * 32u);
        for (int idx = tid; idx < 1536; idx += 256) {
            int c = idx / 24;
            int rem = idx - c * 24;
            int d = rem >> 3, s4 = rem & 7;
            ((float4*)sG)[idx] = gb4[c * 24576 + d * 8192 + s4];
        }
        for (int idx = tid; idx < 2048; idx += 256) {
            ((float4*)sWk)[idx] = ((const float4*)d_WkT)[idx];
            ((float4*)sWv)[idx] = ((const float4*)d_WvT)[idx];
        }
        for (int idx = tid; idx < 384; idx += 256) {
            sQ[idx] = d_q[p * 384 + idx];
            sWstd[idx] = Wstd[idx];
        }
        if (tid < 128) sWr[tid] = d_Wr[tid];
        if (tid < 96) {
            int d = tid >> 5, s = tid & 31;
            sXr[tid] = gxyz[((size_t)p * 32 + s) * 3 + d] - qxyz[(size_t)p * 3 + d];
        }
    }
    __syncthreads();

    const int s = tid & 31, r = tid >> 5, o0 = r << 4;

    // ---- phase 2: k, v via packed FFMA2 (pairs over o) ----
    // atp[jp][d] holds outputs (o0+2jp, o0+2jp+1) for dim d. Same for vpp.
    unsigned long long atp[8][3], vpp[8][3];
#pragma unroll
    for (int jp = 0; jp < 8; jp++)
#pragma unroll
        for (int d = 0; d < 3; d++) { atp[jp][d] = 0ull; vpp[jp][d] = 0ull; }

#pragma unroll 2
    for (int c = 0; c < 64; c++) {
        unsigned long long g0p = pack2(sG[c * 96 + s]);
        unsigned long long g1p = pack2(sG[c * 96 + 32 + s]);
        unsigned long long g2p = pack2(sG[c * 96 + 64 + s]);
        const ulonglong2* wk2 = (const ulonglong2*)(sWk + c * 128 + o0);
        const ulonglong2* wv2 = (const ulonglong2*)(sWv + c * 128 + o0);
#pragma unroll
        for (int j = 0; j < 4; j++) {
            ulonglong2 wk = wk2[j];
            ulonglong2 wv = wv2[j];
            int jp = j * 2;
            ffma2(atp[jp][0], wk.x, g0p); ffma2(atp[jp][1], wk.x, g1p); ffma2(atp[jp][2], wk.x, g2p);
            ffma2(atp[jp + 1][0], wk.y, g0p); ffma2(atp[jp + 1][1], wk.y, g1p); ffma2(atp[jp + 1][2], wk.y, g2p);
            ffma2(vpp[jp][0], wv.x, g0p); ffma2(vpp[jp][1], wv.x, g1p); ffma2(vpp[jp][2], wv.x, g2p);
            ffma2(vpp[jp + 1][0], wv.y, g0p); ffma2(vpp[jp + 1][1], wv.y, g1p); ffma2(vpp[jp + 1][2], wv.y, g2p);
        }
    }

    // ---- phase 3: attn = q - k + pr ; vpr = v + pr (unpack pairs) ----
    float at[16][3], vp[16][3];
#pragma unroll
    for (int jp = 0; jp < 8; jp++) {
        int ia = jp * 2, ib = jp * 2 + 1;
        float wra = sWr[o0 + ia], wrb = sWr[o0 + ib];
#pragma unroll
        for (int d = 0; d < 3; d++) {
            float2 kk = unpack2(atp[jp][d]);
            float2 vv = unpack2(vpp[jp][d]);
            float xr = sXr[d * 32 + s];
            float pra = wra * xr, prb = wrb * xr;
            at[ia][d] = sQ[(o0 + ia) * 3 + d] - kk.x + pra;
            at[ib][d] = sQ[(o0 + ib) * 3 + d] - kk.y + prb;
            vp[ia][d] = vv.x + pra;
            vp[ib][d] = vv.y + prb;
        }
    }
    __syncthreads();   // all reads of sG/sWk/sWv complete before aliased writes

#pragma unroll
    for (int i = 0; i < 16; i++) {
        sVpr[(o0 + i) * 96 + s]      = vp[i][0];
        sVpr[(o0 + i) * 96 + 32 + s] = vp[i][1];
        sVpr[(o0 + i) * 96 + 64 + s] = vp[i][2];
    }

    // ---- phase 4: z0 partials ----
    {
        float pz[9];
#pragma unroll
        for (int jk = 0; jk < 9; jk++) pz[jk] = 0.f;
#pragma unroll
        for (int i = 0; i < 16; i++) {
            float w0 = sWstd[o0 + i];
            float w1 = sWstd[128 + o0 + i];
            float w2 = sWstd[256 + o0 + i];
#pragma unroll
            for (int k = 0; k < 3; k++) {
                float a = at[i][k];
                pz[0 * 3 + k] += w0 * a;
                pz[1 * 3 + k] += w1 * a;
                pz[2 * 3 + k] += w2 * a;
            }
        }
#pragma unroll
        for (int jk = 0; jk < 9; jk++) sZp[(r * 32 + s) * 9 + jk] = pz[jk];
    }
    __syncthreads();
    if (r == 0) {
#pragma unroll
        for (int jk = 0; jk < 9; jk++) {
            float v = 0.f;
#pragma unroll
            for (int rr = 0; rr < 8; rr++) v += sZp[(rr * 32 + s) * 9 + jk];
            sZ[jk * 32 + s] = v;
        }
    }
    __syncthreads();

    // ---- phase 6: attn2 = attn @ z0, store flattened [384][32] ----
    {
        float z[9];
#pragma unroll
        for (int jk = 0; jk < 9; jk++) z[jk] = sZ[jk * 32 + s];
#pragma unroll
        for (int i = 0; i < 16; i++) {
#pragma unroll
            for (int k = 0; k < 3; k++) {
                float a2 = at[i][0] * z[0 * 3 + k] + at[i][1] * z[1 * 3 + k] + at[i][2] * z[2 * 3 + k];
                sA2[((o0 + i) * 3 + k) * 32 + s] = a2;
            }
        }
    }
    __syncthreads();

    // ---- phase 7: f1 (128x384 GEMM over s=32), packed FFMA2 over s-pairs ----
    const int oo = tid & 127, sg = tid >> 7;
    unsigned long long hp[8];
#pragma unroll
    for (int q = 0; q < 8; q++) hp[q] = 0ull;
    for (int ct = 0; ct < 6; ct++) {
        __syncthreads();
        const float4* src = (const float4*)(d_Wf1T + ct * 8192);
        float4* dst = (float4*)sWt;
#pragma unroll
        for (int kk = 0; kk < 8; kk++) dst[tid + kk * 256] = src[tid + kk * 256];
        __syncthreads();
#pragma unroll 2
        for (int cc = 0; cc < 64; cc++) {
            unsigned long long wp = pack2(sWt[cc * 128 + oo]);
            const ulonglong2* av2 = (const ulonglong2*)(sA2 + (ct * 64 + cc) * 32 + sg * 16);
#pragma unroll
            for (int qq = 0; qq < 4; qq++) {
                ulonglong2 a = av2[qq];
                ffma2(hp[qq * 2 + 0], a.x, wp);
                ffma2(hp[qq * 2 + 1], a.y, wp);
            }
        }
    }
    {
        float bb = bf1[oo];
#pragma unroll
        for (int q2 = 0; q2 < 8; q2++) {
            float2 h = unpack2(hp[q2]);
            sH[oo * 36 + sg * 16 + q2 * 2 + 0] = fmaxf(h.x + bb, 0.f);
            sH[oo * 36 + sg * 16 + q2 * 2 + 1] = fmaxf(h.y + bb, 0.f);
        }
    }

    // ---- phase 8: f2 (128x128), packed FFMA2 ----
    unsigned long long ap[8];
#pragma unroll
    for (int q = 0; q < 8; q++) ap[q] = 0ull;
    for (int ct = 0; ct < 2; ct++) {
        __syncthreads();
        const float4* src = (const float4*)(d_Wf2T + ct * 8192);
        float4* dst = (float4*)sWt;
#pragma unroll
        for (int kk = 0; kk < 8; kk++) dst[tid + kk * 256] = src[tid + kk * 256];
        __syncthreads();
#pragma unroll 2
        for (int cc = 0; cc < 64; cc++) {
            unsigned long long wp = pack2(sWt[cc * 128 + oo]);
            const ulonglong2* hv2 = (const ulonglong2*)(sH + (ct * 64 + cc) * 36 + sg * 16);
#pragma unroll
            for (int qq = 0; qq < 4; qq++) {
                ulonglong2 h = hv2[qq];
                ffma2(ap[qq * 2 + 0], h.x, wp);
                ffma2(ap[qq * 2 + 1], h.y, wp);
            }
        }
    }
    {
        float bb = d_bf2s[oo];   // 1/sqrt(128) folded into Wf2T and bf2s
#pragma unroll
        for (int q2 = 0; q2 < 8; q2++) {
            float2 a = unpack2(ap[q2]);
            sAx[oo * 33 + sg * 16 + q2 * 2 + 0] = a.x + bb;
            sAx[oo * 33 + sg * 16 + q2 * 2 + 1] = a.y + bb;
        }
    }
    __syncthreads();

    // ---- phase 9: softmax over s + weighted sum over s ----
    for (int i = 0; i < 16; i++) {
        int o = o0 + i;
        float x = sAx[o * 33 + s];
        float m = wmax(x);
        float e = __expf(x - m);
        float denom = wsum(e);
        float w = e / denom;
#pragma unroll
        for (int d = 0; d < 3; d++) {
            float val = w * sVpr[o * 96 + d * 32 + s];
            float rs = wsum(val);
            if (s == 0) out[(((size_t)b * 128 + o) * 3 + d) * 1024 + n] = rs;
        }
    }
}

extern "C" void kernel_launch(void* const* d_in, const int* in_sizes, int n_in,
                              void* d_out, int out_size) {
    (void)in_sizes; (void)n_in; (void)out_size;
    const float* gxyz = (const float*)d_in[0];
    const float* gfts = (const float*)d_in[1];
    const float* qxyz = (const float*)d_in[2];
    cudaFuncSetAttribute(main_kernel, cudaFuncAttributeMaxDynamicSharedMemorySize, SMEM_BYTES);
    prep1_kernel<<<128, 64>>>((const float*)d_in[3], (const float*)d_in[4]);
    prep2_kernel<<<128, 64>>>((const float*)d_in[5],  (const float*)d_in[6],
                              (const float*)d_in[7],  (const float*)d_in[8],
                              (const float*)d_in[9],  (const float*)d_in[11],
                              (const float*)d_in[13], (const float*)d_in[14]);
    q_kernel<<<NPTS, 128>>>(gfts);
    main_kernel<<<NPTS, 256, SMEM_BYTES>>>(gxyz, gfts, qxyz,
                                           (const float*)d_in[10],
                                           (const float*)d_in[12],
                                           (float*)d_out);
}

// round 6
// speedup vs baseline: 1.2550x; 1.1244x over previous
#include <cuda_runtime.h>

#define NPTS 2048
// main kernel smem: region0 (sG 6144 | sWk 8192 | sWv 8192 = 22528 fl,
// later aliased by sA2 12288 + sH 4608) + smalls 3584 fl = 26112 floats
#define SMEM_FLOATS 26112
#define SMEM_BYTES (SMEM_FLOATS * 4)

// -------- scratch (device globals: allocation-free) --------
__device__ float d_We21[128 * 64];
__device__ float d_WkT[64 * 128];
__device__ float d_WvT[64 * 128];
__device__ float d_WqT[64 * 128];
__device__ float d_Wr[128];
__device__ float d_Wf1T[392 * 128];   // padded +8 rows for prefetch overrun
__device__ float d_Wf2T[136 * 128];   // padded +8 rows
__device__ float d_bf2s[128];
__device__ float d_q[NPTS * 384];
__device__ float d_Ax[NPTS * 128 * 32];          // logits   [p][o][s]
__device__ float d_Vpr[NPTS * 128 * 3 * 32];     // v + pos  [p][o][d][s]

// -------- packed f32x2 helpers (SASS FFMA2 path, PTX-only) --------
__device__ __forceinline__ void ffma2(unsigned long long& d,
                                      unsigned long long a,
                                      unsigned long long b) {
    asm("fma.rn.f32x2 %0, %1, %2, %0;" : "+l"(d) : "l"(a), "l"(b));
}
__device__ __forceinline__ unsigned long long pack2(float x) {
    unsigned long long r;
    asm("mov.b64 %0, {%1, %1};" : "=l"(r) : "f"(x));
    return r;
}
__device__ __forceinline__ float2 unpack2(unsigned long long v) {
    float2 f;
    asm("mov.b64 {%0, %1}, %2;" : "=f"(f.x), "=f"(f.y) : "l"(v));
    return f;
}

// ---------------- prep1: We21 = We2 @ We1  (128x64) ----------------
__global__ void prep1_kernel(const float* __restrict__ We1, const float* __restrict__ We2) {
    int t = blockIdx.x, c = threadIdx.x;
    float a = 0.f;
#pragma unroll 8
    for (int e = 0; e < 128; e++) a += We2[t * 128 + e] * We1[e * 64 + c];
    d_We21[t * 64 + c] = a;
}

// ---------------- prep2: fold q/k/v + transpose f1/f2 + Wr ----------------
__global__ void prep2_kernel(const float* __restrict__ Wq, const float* __restrict__ Wk,
                             const float* __restrict__ Wv, const float* __restrict__ Wr1,
                             const float* __restrict__ Wr2, const float* __restrict__ Wf1,
                             const float* __restrict__ Wf2, const float* __restrict__ bf2) {
    const float invS = 0.08838834764831845f;  // 1/sqrt(128)
    int o = blockIdx.x, c = threadIdx.x;
    float ak = 0.f, av = 0.f, aq = 0.f;
#pragma unroll 8
    for (int x = 0; x < 128; x++) {
        float w21 = d_We21[x * 64 + c];
        ak += Wk[o * 128 + x] * w21;
        av += Wv[o * 128 + x] * w21;
        aq += Wq[o * 128 + x] * w21;
    }
    d_WkT[c * 128 + o] = ak;
    d_WvT[c * 128 + o] = av;
    d_WqT[c * 128 + o] = aq;
#pragma unroll
    for (int u = 0; u < 6; u++) { int cc = u * 64 + c; d_Wf1T[cc * 128 + o] = Wf1[o * 384 + cc]; }
#pragma unroll
    for (int u = 0; u < 2; u++) { int cc = u * 64 + c; d_Wf2T[cc * 128 + o] = Wf2[o * 128 + cc] * invS; }
    __shared__ float red[64];
    red[c] = Wr2[o * 64 + c] * Wr1[c];
    __syncthreads();
    if (c == 0) {
        float r = 0.f;
#pragma unroll
        for (int i = 0; i < 64; i++) r += red[i];
        d_Wr[o] = r;
        d_bf2s[o] = bf2[o] * invS;
    }
    // zero the prefetch-overrun pad rows
    if (o == 0) {
#pragma unroll
        for (int u = 0; u < 8; u++) { d_Wf1T[(384 + u) * 128 + c * 2] = 0.f; d_Wf1T[(384 + u) * 128 + c * 2 + 1] = 0.f; }
#pragma unroll
        for (int u = 0; u < 8; u++) { d_Wf2T[(128 + u) * 128 + c * 2] = 0.f; d_Wf2T[(128 + u) * 128 + c * 2 + 1] = 0.f; }
    }
}

// ---------------- per-point q (from s=0 column of group_fts) ----------------
__global__ void q_kernel(const float* __restrict__ gfts) {
    int p = blockIdx.x;             // b*1024 + n
    int b = p >> 10, n = p & 1023;
    int o = threadIdx.x;            // 128 threads
    const float* gbase = gfts + (size_t)b * 6291456u + (size_t)n * 32u;
    float acc0 = 0.f, acc1 = 0.f, acc2 = 0.f;
#pragma unroll 4
    for (int c = 0; c < 64; c++) {
        float w = d_WqT[c * 128 + o];
        acc0 += w * gbase[c * 98304 + 0 * 32768];
        acc1 += w * gbase[c * 98304 + 1 * 32768];
        acc2 += w * gbase[c * 98304 + 2 * 32768];
    }
    d_q[p * 384 + o * 3 + 0] = acc0;
    d_q[p * 384 + o * 3 + 1] = acc1;
    d_q[p * 384 + o * 3 + 2] = acc2;
}

// ---------------- warp reductions ----------------
__device__ __forceinline__ float wmax(float v) {
#pragma unroll
    for (int m = 16; m; m >>= 1) v = fmaxf(v, __shfl_xor_sync(0xffffffffu, v, m));
    return v;
}
__device__ __forceinline__ float wsum(float v) {
#pragma unroll
    for (int m = 16; m; m >>= 1) v += __shfl_xor_sync(0xffffffffu, v, m);
    return v;
}

// ---------------- main kernel: one CTA per point, 2 CTAs/SM ----------------
__global__ __launch_bounds__(256, 2)
void main_kernel(const float* __restrict__ gxyz, const float* __restrict__ gfts,
                 const float* __restrict__ qxyz, const float* __restrict__ Wstd,
                 const float* __restrict__ bf1) {
    extern __shared__ float smf[];
    float* sG    = smf;             // [64][3][32]  phase A        (6144)
    float* sWk   = smf + 6144;      // [64][128]    phase A        (8192)
    float* sWv   = smf + 14336;     // [64][128]    phase A        (8192)
    float* sA2   = smf;             // [384][32]    phase B alias  (12288)
    float* sH    = smf + 12544;     // [128][36]    phase B alias  (4608, inside region0)
    float* sXr   = smf + 22528;     // [3][32]
    float* sQ    = smf + 22624;     // [384]
    float* sWr   = smf + 23008;     // [128]
    float* sWstd = smf + 23136;     // [3][128]
    float* sZp   = smf + 23520;     // [8][32][9]
    float* sZ    = smf + 25824;     // [9][32]

    const int p = blockIdx.x;
    const int b = p >> 10, n = p & 1023;
    const int tid = threadIdx.x;

    // ---- cooperative loads ----
    {
        const float4* gb4 = (const float4*)(gfts + (size_t)b * 6291456u + (size_t)n * 32u);
        for (int idx = tid; idx < 1536; idx += 256) {
            int c = idx / 24;
            int rem = idx - c * 24;
            int d = rem >> 3, s4 = rem & 7;
            ((float4*)sG)[idx] = gb4[c * 24576 + d * 8192 + s4];
        }
        for (int idx = tid; idx < 2048; idx += 256) {
            ((float4*)sWk)[idx] = ((const float4*)d_WkT)[idx];
            ((float4*)sWv)[idx] = ((const float4*)d_WvT)[idx];
        }
        for (int idx = tid; idx < 384; idx += 256) {
            sQ[idx] = d_q[p * 384 + idx];
            sWstd[idx] = Wstd[idx];
        }
        if (tid < 128) sWr[tid] = d_Wr[tid];
        if (tid < 96) {
            int d = tid >> 5, s = tid & 31;
            sXr[tid] = gxyz[((size_t)p * 32 + s) * 3 + d] - qxyz[(size_t)p * 3 + d];
        }
    }
    __syncthreads();

    const int s = tid & 31, r = tid >> 5, o0 = r << 4;

    // ---- phase 2: k, v via packed FFMA2 (pairs over o) ----
    unsigned long long atp[8][3], vpp[8][3];
#pragma unroll
    for (int jp = 0; jp < 8; jp++)
#pragma unroll
        for (int d = 0; d < 3; d++) { atp[jp][d] = 0ull; vpp[jp][d] = 0ull; }

#pragma unroll 2
    for (int c = 0; c < 64; c++) {
        unsigned long long g0p = pack2(sG[c * 96 + s]);
        unsigned long long g1p = pack2(sG[c * 96 + 32 + s]);
        unsigned long long g2p = pack2(sG[c * 96 + 64 + s]);
        const ulonglong2* wk2 = (const ulonglong2*)(sWk + c * 128 + o0);
        const ulonglong2* wv2 = (const ulonglong2*)(sWv + c * 128 + o0);
#pragma unroll
        for (int j = 0; j < 4; j++) {
            ulonglong2 wk = wk2[j];
            ulonglong2 wv = wv2[j];
            int jp = j * 2;
            ffma2(atp[jp][0], wk.x, g0p); ffma2(atp[jp][1], wk.x, g1p); ffma2(atp[jp][2], wk.x, g2p);
            ffma2(atp[jp + 1][0], wk.y, g0p); ffma2(atp[jp + 1][1], wk.y, g1p); ffma2(atp[jp + 1][2], wk.y, g2p);
            ffma2(vpp[jp][0], wv.x, g0p); ffma2(vpp[jp][1], wv.x, g1p); ffma2(vpp[jp][2], wv.x, g2p);
            ffma2(vpp[jp + 1][0], wv.y, g0p); ffma2(vpp[jp + 1][1], wv.y, g1p); ffma2(vpp[jp + 1][2], wv.y, g2p);
        }
    }

    // ---- phase 3: attn = q - k + pr (regs); vpr = v + pr -> GLOBAL ----
    float at[16][3];
    {
        float* vout = d_Vpr + (size_t)(p * 128 + o0) * 96 + s;
#pragma unroll
        for (int jp = 0; jp < 8; jp++) {
            int ia = jp * 2, ib = jp * 2 + 1;
            float wra = sWr[o0 + ia], wrb = sWr[o0 + ib];
#pragma unroll
            for (int d = 0; d < 3; d++) {
                float2 kk = unpack2(atp[jp][d]);
                float2 vv = unpack2(vpp[jp][d]);
                float xr = sXr[d * 32 + s];
                float pra = wra * xr, prb = wrb * xr;
                at[ia][d] = sQ[(o0 + ia) * 3 + d] - kk.x + pra;
                at[ib][d] = sQ[(o0 + ib) * 3 + d] - kk.y + prb;
                vout[ia * 96 + d * 32] = vv.x + pra;
                vout[ib * 96 + d * 32] = vv.y + prb;
            }
        }
    }

    // ---- phase 4: z0 partials ----
    {
        float pz[9];
#pragma unroll
        for (int jk = 0; jk < 9; jk++) pz[jk] = 0.f;
#pragma unroll
        for (int i = 0; i < 16; i++) {
            float w0 = sWstd[o0 + i];
            float w1 = sWstd[128 + o0 + i];
            float w2 = sWstd[256 + o0 + i];
#pragma unroll
            for (int k = 0; k < 3; k++) {
                float a = at[i][k];
                pz[0 * 3 + k] += w0 * a;
                pz[1 * 3 + k] += w1 * a;
                pz[2 * 3 + k] += w2 * a;
            }
        }
#pragma unroll
        for (int jk = 0; jk < 9; jk++) sZp[(r * 32 + s) * 9 + jk] = pz[jk];
    }
    __syncthreads();                 // also fences last sG/sWk/sWv reads before sA2 alias writes
    if (r == 0) {
#pragma unroll
        for (int jk = 0; jk < 9; jk++) {
            float v = 0.f;
#pragma unroll
            for (int rr = 0; rr < 8; rr++) v += sZp[(rr * 32 + s) * 9 + jk];
            sZ[jk * 32 + s] = v;
        }
    }
    __syncthreads();

    // ---- phase 6: attn2 = attn @ z0 -> sA2 [384][32] (aliases sG/sWk) ----
    {
        float z[9];
#pragma unroll
        for (int jk = 0; jk < 9; jk++) z[jk] = sZ[jk * 32 + s];
#pragma unroll
        for (int i = 0; i < 16; i++) {
#pragma unroll
            for (int k = 0; k < 3; k++) {
                float a2 = at[i][0] * z[0 * 3 + k] + at[i][1] * z[1 * 3 + k] + at[i][2] * z[2 * 3 + k];
                sA2[((o0 + i) * 3 + k) * 32 + s] = a2;
            }
        }
    }
    __syncthreads();

    // ---- phase 7: f1 GEMM 128x384 over s=32; weights streamed from L2 w/ prefetch ----
    const int oo = tid & 127, sg = tid >> 7;
    unsigned long long hp[8];
#pragma unroll
    for (int q = 0; q < 8; q++) hp[q] = 0ull;
    {
        float wc[4], wn[4];
#pragma unroll
        for (int j = 0; j < 4; j++) wc[j] = d_Wf1T[j * 128 + oo];
        for (int cb = 0; cb < 384; cb += 4) {
#pragma unroll
            for (int j = 0; j < 4; j++) wn[j] = d_Wf1T[(cb + 4 + j) * 128 + oo];
#pragma unroll
            for (int j = 0; j < 4; j++) {
                unsigned long long wp = pack2(wc[j]);
                const ulonglong2* av2 = (const ulonglong2*)(sA2 + (cb + j) * 32 + sg * 16);
#pragma unroll
                for (int qq = 0; qq < 4; qq++) {
                    ulonglong2 a = av2[qq];
                    ffma2(hp[qq * 2 + 0], a.x, wp);
                    ffma2(hp[qq * 2 + 1], a.y, wp);
                }
            }
#pragma unroll
            for (int j = 0; j < 4; j++) wc[j] = wn[j];
        }
    }
    {
        float bb = bf1[oo];
#pragma unroll
        for (int q2 = 0; q2 < 8; q2++) {
            float2 h = unpack2(hp[q2]);
            sH[oo * 36 + sg * 16 + q2 * 2 + 0] = fmaxf(h.x + bb, 0.f);
            sH[oo * 36 + sg * 16 + q2 * 2 + 1] = fmaxf(h.y + bb, 0.f);
        }
    }
    __syncthreads();

    // ---- phase 8: f2 GEMM 128x128; logits -> GLOBAL ----
    unsigned long long ap[8];
#pragma unroll
    for (int q = 0; q < 8; q++) ap[q] = 0ull;
    {
        float wc[4], wn[4];
#pragma unroll
        for (int j = 0; j < 4; j++) wc[j] = d_Wf2T[j * 128 + oo];
        for (int cb = 0; cb < 128; cb += 4) {
#pragma unroll
            for (int j = 0; j < 4; j++) wn[j] = d_Wf2T[(cb + 4 + j) * 128 + oo];
#pragma unroll
            for (int j = 0; j < 4; j++) {
                unsigned long long wp = pack2(wc[j]);
                const ulonglong2* hv2 = (const ulonglong2*)(sH + (cb + j) * 36 + sg * 16);
#pragma unroll
                for (int qq = 0; qq < 4; qq++) {
                    ulonglong2 h = hv2[qq];
                    ffma2(ap[qq * 2 + 0], h.x, wp);
                    ffma2(ap[qq * 2 + 1], h.y, wp);
                }
            }
#pragma unroll
            for (int j = 0; j < 4; j++) wc[j] = wn[j];
        }
    }
    {
        float bb = d_bf2s[oo];   // 1/sqrt(128) folded into Wf2T and bf2s
        float4* axo = (float4*)(d_Ax + (size_t)(p * 128 + oo) * 32 + sg * 16);
#pragma unroll
        for (int q4 = 0; q4 < 4; q4++) {
            float2 a0 = unpack2(ap[q4 * 2 + 0]);
            float2 a1 = unpack2(ap[q4 * 2 + 1]);
            axo[q4] = make_float4(a0.x + bb, a0.y + bb, a1.x + bb, a1.y + bb);
        }
    }
}

// ---------------- finish: softmax over s + weighted sum over s ----------------
__global__ __launch_bounds__(256)
void finish_kernel(float* __restrict__ out) {
    const int p = blockIdx.x;
    const int b = p >> 10, n = p & 1023;
    const int tid = threadIdx.x;
    const int s = tid & 31, r = tid >> 5, o0 = r << 4;
    const float* ax = d_Ax + (size_t)(p * 128) * 32 + s;
    const float* vr = d_Vpr + (size_t)(p * 128) * 96 + s;
#pragma unroll 2
    for (int i = 0; i < 16; i++) {
        int o = o0 + i;
        float x = ax[o * 32];
        float v0 = vr[o * 96];
        float v1 = vr[o * 96 + 32];
        float v2 = vr[o * 96 + 64];
        float m = wmax(x);
        float e = __expf(x - m);
        float denom = wsum(e);
        float w = e / denom;
        float r0 = wsum(w * v0);
        float r1 = wsum(w * v1);
        float r2 = wsum(w * v2);
        if (s == 0) {
            size_t base = (((size_t)b * 128 + o) * 3) * 1024 + n;
            out[base] = r0;
            out[base + 1024] = r1;
            out[base + 2048] = r2;
        }
    }
}

extern "C" void kernel_launch(void* const* d_in, const int* in_sizes, int n_in,
                              void* d_out, int out_size) {
    (void)in_sizes; (void)n_in; (void)out_size;
    const float* gxyz = (const float*)d_in[0];
    const float* gfts = (const float*)d_in[1];
    const float* qxyz = (const float*)d_in[2];
    cudaFuncSetAttribute(main_kernel, cudaFuncAttributeMaxDynamicSharedMemorySize, SMEM_BYTES);
    prep1_kernel<<<128, 64>>>((const float*)d_in[3], (const float*)d_in[4]);
    prep2_kernel<<<128, 64>>>((const float*)d_in[5],  (const float*)d_in[6],
                              (const float*)d_in[7],  (const float*)d_in[8],
                              (const float*)d_in[9],  (const float*)d_in[11],
                              (const float*)d_in[13], (const float*)d_in[14]);
    q_kernel<<<NPTS, 128>>>(gfts);
    main_kernel<<<NPTS, 256, SMEM_BYTES>>>(gxyz, gfts, qxyz,
                                           (const float*)d_in[10],
                                           (const float*)d_in[12]);
    finish_kernel<<<NPTS, 256>>>((float*)d_out);
}